// round 14
// baseline (speedup 1.0000x reference)
#include <cuda_runtime.h>
#include <cuda_bf16.h>
#include <mma.h>
#include <math.h>
#include <math_constants.h>
#include <stdint.h>

using namespace nvcuda;

#define BD   2
#define SD   2048
#define DD   1024
#define HD   16
#define DKD  64
#define HID  4
#define DID  64
#define KTOP 512
#define ROWS (BD*SD)

// ---------------- scratch ----------------
__device__ float g_qkv[(size_t)ROWS * 3 * DD];
__device__ float g_qi [(size_t)ROWS * HID * DID];
__device__ float g_ki [(size_t)ROWS * DID];
__device__ float g_wi [(size_t)ROWS * HID];
__device__ unsigned short g_topidx[(size_t)ROWS * KTOP];
__device__ float g_attn[(size_t)ROWS * DD];

// ---------------- WMMA bf16 3-term-split GEMM (R13 verbatim, FULL K) ----------------
__global__ __launch_bounds__(256) void wmma_gemm(
    const float* __restrict__ A, const float* __restrict__ B,
    float* __restrict__ C, int N)
{
    __shared__ __align__(256) __nv_bfloat16 sA1[128 * 40];
    __shared__ __align__(256) __nv_bfloat16 sA2[128 * 40];
    __shared__ __align__(256) __nv_bfloat16 sB1[128 * 40];
    __shared__ __align__(256) __nv_bfloat16 sB2[128 * 40];
    const int LDS_ELE = 40;
    int tid = threadIdx.x, wid = tid >> 5;
    int bm = blockIdx.y * 128, bn = blockIdx.x * 128;
    int wm = (wid & 3) * 32, wn = (wid >> 2) * 64;

    wmma::fragment<wmma::accumulator, 16, 16, 16, float> acc[2][4];
    #pragma unroll
    for (int mt = 0; mt < 2; mt++)
        #pragma unroll
        for (int nt = 0; nt < 4; nt++)
            wmma::fill_fragment(acc[mt][nt], 0.0f);

    for (int c = 0; c < 32; c++) {
        int k0 = c * 32;
        #pragma unroll
        for (int p = 0; p < 4; p++) {
            int idx = tid + p * 256;
            int row = idx >> 3;
            int cg  = idx & 7;
            int so  = row * LDS_ELE + cg * 4;
            float4 av = *(const float4*)(A + (size_t)(bm + row) * 1024 + k0 + cg * 4);
            __nv_bfloat16 hx = __float2bfloat16(av.x), hy = __float2bfloat16(av.y);
            __nv_bfloat16 hz = __float2bfloat16(av.z), hw = __float2bfloat16(av.w);
            sA1[so] = hx; sA1[so + 1] = hy; sA1[so + 2] = hz; sA1[so + 3] = hw;
            sA2[so]     = __float2bfloat16(av.x - __bfloat162float(hx));
            sA2[so + 1] = __float2bfloat16(av.y - __bfloat162float(hy));
            sA2[so + 2] = __float2bfloat16(av.z - __bfloat162float(hz));
            sA2[so + 3] = __float2bfloat16(av.w - __bfloat162float(hw));
            float4 bv = *(const float4*)(B + (size_t)(bn + row) * 1024 + k0 + cg * 4);
            __nv_bfloat16 gx = __float2bfloat16(bv.x), gy = __float2bfloat16(bv.y);
            __nv_bfloat16 gz = __float2bfloat16(bv.z), gw = __float2bfloat16(bv.w);
            sB1[so] = gx; sB1[so + 1] = gy; sB1[so + 2] = gz; sB1[so + 3] = gw;
            sB2[so]     = __float2bfloat16(bv.x - __bfloat162float(gx));
            sB2[so + 1] = __float2bfloat16(bv.y - __bfloat162float(gy));
            sB2[so + 2] = __float2bfloat16(bv.z - __bfloat162float(gz));
            sB2[so + 3] = __float2bfloat16(bv.w - __bfloat162float(gw));
        }
        __syncthreads();
        #pragma unroll
        for (int kk = 0; kk < 32; kk += 16) {
            wmma::fragment<wmma::matrix_a, 16, 16, 16, __nv_bfloat16, wmma::row_major> a1f[2], a2f[2];
            #pragma unroll
            for (int mt = 0; mt < 2; mt++) {
                int off = (wm + mt * 16) * LDS_ELE + kk;
                wmma::load_matrix_sync(a1f[mt], sA1 + off, LDS_ELE);
                wmma::load_matrix_sync(a2f[mt], sA2 + off, LDS_ELE);
            }
            #pragma unroll
            for (int nt = 0; nt < 4; nt++) {
                int off = (wn + nt * 16) * LDS_ELE + kk;
                wmma::fragment<wmma::matrix_b, 16, 16, 16, __nv_bfloat16, wmma::col_major> b1f, b2f;
                wmma::load_matrix_sync(b1f, sB1 + off, LDS_ELE);
                wmma::load_matrix_sync(b2f, sB2 + off, LDS_ELE);
                #pragma unroll
                for (int mt = 0; mt < 2; mt++) {
                    wmma::mma_sync(acc[mt][nt], a1f[mt], b1f, acc[mt][nt]);
                    wmma::mma_sync(acc[mt][nt], a1f[mt], b2f, acc[mt][nt]);
                    wmma::mma_sync(acc[mt][nt], a2f[mt], b1f, acc[mt][nt]);
                }
            }
        }
        __syncthreads();
    }

    #pragma unroll
    for (int mt = 0; mt < 2; mt++)
        #pragma unroll
        for (int nt = 0; nt < 4; nt++) {
            float* cp = C + (size_t)(bm + wm + mt * 16) * N + bn + wn + nt * 16;
            wmma::store_matrix_sync(cp, acc[mt][nt], N, wmma::mem_row_major);
        }
}

// ---------------- small fused SGEMM (qi, ki, wi) — exact fp32 ----------------
__global__ void gemm_small_fused(const float* __restrict__ A,
                                 const float* __restrict__ B0, const float* __restrict__ B1,
                                 const float* __restrict__ B2,
                                 float* __restrict__ C0, float* __restrict__ C1,
                                 float* __restrict__ C2, int M, int Kd)
{
    const float* B; float* C; int N;
    if (blockIdx.z == 0)      { B = B0; C = C0; N = 256; }
    else if (blockIdx.z == 1) { B = B1; C = C1; N = 64;  }
    else                      { B = B2; C = C2; N = 4;   }
    int bn = blockIdx.x * 64;
    if (bn >= N) return;

    __shared__ float As[16][65];
    __shared__ float Bs[16][65];
    int tid = threadIdx.x;
    int tx = tid & 15, ty = tid >> 4;
    int bm = blockIdx.y * 64;
    float acc[4][4] = {};
    for (int k0 = 0; k0 < Kd; k0 += 16) {
        #pragma unroll
        for (int i = 0; i < 4; i++) {
            int idx = tid + i * 256;
            int m = idx >> 4, k = idx & 15;
            As[k][m] = A[(size_t)(bm + m) * Kd + k0 + k];
            int gn = bn + m;
            Bs[k][m] = (gn < N) ? B[(size_t)gn * Kd + k0 + k] : 0.0f;
        }
        __syncthreads();
        #pragma unroll
        for (int k = 0; k < 16; k++) {
            float a[4], b[4];
            #pragma unroll
            for (int i = 0; i < 4; i++) a[i] = As[k][ty * 4 + i];
            #pragma unroll
            for (int j = 0; j < 4; j++) b[j] = Bs[k][tx * 4 + j];
            #pragma unroll
            for (int i = 0; i < 4; i++)
                #pragma unroll
                for (int j = 0; j < 4; j++)
                    acc[i][j] = fmaf(a[i], b[j], acc[i][j]);
        }
        __syncthreads();
    }
    #pragma unroll
    for (int i = 0; i < 4; i++) {
        int gm = bm + ty * 4 + i;
        #pragma unroll
        for (int j = 0; j < 4; j++) {
            int gn = bn + tx * 4 + j;
            if (gn < N) C[(size_t)gm * N + gn] = acc[i][j];
        }
    }
}

// ---------------- RoPE ----------------
__global__ void rope_kernel(float* __restrict__ qkv) {
    int idx = blockIdx.x * blockDim.x + threadIdx.x;
    if (idx >= ROWS * HD * 32) return;
    int i  = idx & 31;
    int h  = (idx >> 5) & 15;
    int ts = idx >> 9;
    int t  = ts & (SD - 1);
    float inv = (float)(1.0 / pow(10000.0, (double)(2 * i) / 64.0));
    float ang = (float)t * inv;
    float c = cosf(ang), s = sinf(ang);
    size_t base = (size_t)ts * 3072 + h * 64 + 2 * i;
    float x1 = qkv[base], x2 = qkv[base + 1];
    qkv[base]     = x1 * c - x2 * s;
    qkv[base + 1] = x1 * s + x2 * c;
    x1 = qkv[base + 1024]; x2 = qkv[base + 1025];
    qkv[base + 1024] = x1 * c - x2 * s;
    qkv[base + 1025] = x1 * s + x2 * c;
}

__device__ __forceinline__ unsigned int fkey(float f) {
    unsigned int u = __float_as_uint(f);
    return (u & 0x80000000u) ? ~u : (u | 0x80000000u);
}

// ---------------- indexer + exact top-k (register-blocked: 8x less q-LDS) ----------------
// Per-key accumulation order unchanged (d4 ascending; x,y,z,w; per-head acc) -> scores
// bit-identical to R13 -> identical top-k selection.
__global__ void indexer_topk(const float* __restrict__ qi, const float* __restrict__ ki,
                             const float* __restrict__ wi, unsigned short* __restrict__ topidx) {
    int r = blockIdx.x;
    int b = r >> 11;
    int t = r & (SD - 1);
    int tid = threadIdx.x;
    __shared__ float sc[SD];
    __shared__ __align__(16) float qis[HID * DID];
    __shared__ float wis[HID];
    __shared__ unsigned int hist[256];
    __shared__ unsigned int scanbuf[256];
    __shared__ unsigned int sh_prefix, sh_kneed, sh_outcnt;

    qis[tid] = qi[(size_t)r * 256 + tid];
    if (tid < 4) wis[tid] = wi[r * 4 + tid];
    if (tid == 0) { sh_prefix = 0u; sh_kneed = KTOP; sh_outcnt = 0u; }
    __syncthreads();

    const float* kbase = ki + (size_t)b * SD * DID;
    const float4* q4 = (const float4*)qis;
    {
        int s0 = tid * 8;
        float acc[8][4];
        #pragma unroll
        for (int kk = 0; kk < 8; kk++)
            #pragma unroll
            for (int hh = 0; hh < 4; hh++) acc[kk][hh] = 0.f;

        const float4* k4 = (const float4*)(kbase + (size_t)s0 * DID);
        #pragma unroll
        for (int d4 = 0; d4 < 16; d4++) {
            float4 a0 = q4[d4], a1 = q4[16 + d4], a2 = q4[32 + d4], a3 = q4[48 + d4];
            #pragma unroll
            for (int kk = 0; kk < 8; kk++) {
                float4 kv = k4[kk * 16 + d4];
                acc[kk][0] = fmaf(a0.x, kv.x, acc[kk][0]);
                acc[kk][0] = fmaf(a0.y, kv.y, acc[kk][0]);
                acc[kk][0] = fmaf(a0.z, kv.z, acc[kk][0]);
                acc[kk][0] = fmaf(a0.w, kv.w, acc[kk][0]);
                acc[kk][1] = fmaf(a1.x, kv.x, acc[kk][1]);
                acc[kk][1] = fmaf(a1.y, kv.y, acc[kk][1]);
                acc[kk][1] = fmaf(a1.z, kv.z, acc[kk][1]);
                acc[kk][1] = fmaf(a1.w, kv.w, acc[kk][1]);
                acc[kk][2] = fmaf(a2.x, kv.x, acc[kk][2]);
                acc[kk][2] = fmaf(a2.y, kv.y, acc[kk][2]);
                acc[kk][2] = fmaf(a2.z, kv.z, acc[kk][2]);
                acc[kk][2] = fmaf(a2.w, kv.w, acc[kk][2]);
                acc[kk][3] = fmaf(a3.x, kv.x, acc[kk][3]);
                acc[kk][3] = fmaf(a3.y, kv.y, acc[kk][3]);
                acc[kk][3] = fmaf(a3.z, kv.z, acc[kk][3]);
                acc[kk][3] = fmaf(a3.w, kv.w, acc[kk][3]);
            }
        }
        #pragma unroll
        for (int kk = 0; kk < 8; kk++) {
            int s = s0 + kk;
            float val;
            if (s > t) {
                val = -CUDART_INF_F;
            } else {
                val = fmaxf(acc[kk][0], 0.f) * wis[0] + fmaxf(acc[kk][1], 0.f) * wis[1]
                    + fmaxf(acc[kk][2], 0.f) * wis[2] + fmaxf(acc[kk][3], 0.f) * wis[3];
                val += 0.0f;
            }
            sc[s] = val;
        }
    }
    __syncthreads();

    unsigned int prefix = 0, maskdone = 0;
    for (int shift = 24; shift >= 0; shift -= 8) {
        hist[tid] = 0;
        __syncthreads();
        for (int rr = 0; rr < 8; rr++) {
            int s = tid * 8 + rr;
            unsigned int key = fkey(sc[s]);
            if ((key & maskdone) == prefix) atomicAdd(&hist[(key >> shift) & 255], 1u);
        }
        __syncthreads();
        if (tid == 0) {
            unsigned int kneed = sh_kneed, c = 0;
            int bsel = 0;
            for (int bb = 255; bb >= 0; bb--) {
                unsigned int c2 = c + hist[bb];
                if (c2 >= kneed) { bsel = bb; break; }
                c = c2;
            }
            sh_kneed  = kneed - c;
            sh_prefix = sh_prefix | ((unsigned int)bsel << shift);
        }
        __syncthreads();
        prefix = sh_prefix;
        maskdone |= (255u << shift);
    }
    unsigned int T    = prefix;
    unsigned int n_eq = sh_kneed;

    unsigned int eqc = 0;
    for (int rr = 0; rr < 8; rr++) {
        int s = tid * 8 + rr;
        if (fkey(sc[s]) == T) eqc++;
    }
    scanbuf[tid] = eqc;
    __syncthreads();
    for (int off = 1; off < 256; off <<= 1) {
        unsigned int v = scanbuf[tid];
        unsigned int add = (tid >= off) ? scanbuf[tid - off] : 0u;
        __syncthreads();
        scanbuf[tid] = v + add;
        __syncthreads();
    }
    unsigned int rank = scanbuf[tid] - eqc;

    unsigned short* outp = topidx + (size_t)r * KTOP;
    for (int rr = 0; rr < 8; rr++) {
        int s = tid * 8 + rr;
        unsigned int key = fkey(sc[s]);
        if (key > T) {
            unsigned int p = atomicAdd(&sh_outcnt, 1u);
            outp[p] = (unsigned short)s;
        } else if (key == T) {
            if (rank < n_eq) {
                unsigned int p = atomicAdd(&sh_outcnt, 1u);
                outp[p] = (unsigned short)s;
            }
            rank++;
        }
    }
}

// ---------------- gathered sparse attention (8-deep MLP both phases) ----------------
__global__ void attn_kernel(const float* __restrict__ qkv,
                            const unsigned short* __restrict__ topidx,
                            float* __restrict__ attn_out) {
    int h   = blockIdx.x;
    int row = blockIdx.y;
    int b   = row >> 11;
    int tid  = threadIdx.x;
    int lane = tid & 31, w = tid >> 5;

    __shared__ float q[64];
    __shared__ float sc[KTOP];
    __shared__ int   sidx[KTOP];
    __shared__ float redm[4], redsum[4];
    __shared__ float part[128];

    const unsigned short* ip = topidx + (size_t)row * KTOP;
    #pragma unroll
    for (int r = 0; r < 4; r++) sidx[tid + 128 * r] = (int)ip[tid + 128 * r];
    if (tid < 64) q[tid] = qkv[(size_t)row * 3072 + h * 64 + tid];
    __syncthreads();

    // score phase: warp w -> keys [w*128, w*128+128); 8 keys in flight
    float qx = q[2 * lane], qy = q[2 * lane + 1];
    const float* kb = qkv + (size_t)b * SD * 3072 + 1024 + h * 64 + 2 * lane;
    float mloc = -CUDART_INF_F;
    int j0 = w * 128;
    for (int jj = 0; jj < 128; jj += 8) {
        int j = j0 + jj;
        float d[8];
        #pragma unroll
        for (int u = 0; u < 8; u++) {
            float2 kv = *(const float2*)(kb + (size_t)sidx[j + u] * 3072);
            d[u] = fmaf(qx, kv.x, qy * kv.y);
        }
        #pragma unroll
        for (int u = 0; u < 8; u++) {
            #pragma unroll
            for (int o = 16; o; o >>= 1) d[u] += __shfl_xor_sync(0xffffffffu, d[u], o);
            d[u] *= 0.125f;
            mloc = fmaxf(mloc, d[u]);
        }
        if (lane < 8) sc[j + lane] = d[lane];
    }
    if (lane == 0) redm[w] = mloc;
    __syncthreads();
    float m = fmaxf(fmaxf(redm[0], redm[1]), fmaxf(redm[2], redm[3]));

    float sloc = 0.f;
    #pragma unroll
    for (int r = 0; r < 4; r++) {
        int j = tid + 128 * r;
        float e = expf(sc[j] - m);
        sc[j] = e;
        sloc += e;
    }
    #pragma unroll
    for (int o = 16; o; o >>= 1) sloc += __shfl_xor_sync(0xffffffffu, sloc, o);
    if (lane == 0) redsum[w] = sloc;
    __syncthreads();
    float inv = 1.0f / (redsum[0] + redsum[1] + redsum[2] + redsum[3]);

    // V phase: 8 independent accumulators, 8 loads in flight
    int d    = tid & 63;
    int half = tid >> 6;
    const float* vb = qkv + (size_t)b * SD * 3072 + 2048 + h * 64 + d;
    float a[8];
    #pragma unroll
    for (int u = 0; u < 8; u++) a[u] = 0.f;
    int jb = half * 256;
    for (int j = jb; j < jb + 256; j += 8) {
        #pragma unroll
        for (int u = 0; u < 8; u++)
            a[u] = fmaf(sc[j + u], vb[(size_t)sidx[j + u] * 3072], a[u]);
    }
    part[tid] = ((a[0] + a[1]) + (a[2] + a[3])) + ((a[4] + a[5]) + (a[6] + a[7]));
    __syncthreads();
    if (tid < 64)
        attn_out[(size_t)row * DD + h * 64 + tid] = (part[tid] + part[tid + 64]) * inv;
}

// ---------------- launch ----------------
extern "C" void kernel_launch(void* const* d_in, const int* in_sizes, int n_in,
                              void* d_out, int out_size) {
    const float* x     = (const float*)d_in[0];
    const float* w_qkv = (const float*)d_in[1];
    const float* w_o   = (const float*)d_in[2];
    const float* w_qi  = (const float*)d_in[3];
    const float* w_ki  = (const float*)d_in[4];
    const float* w_wi  = (const float*)d_in[5];
    float* out = (float*)d_out;

    void *p_qkv, *p_qi, *p_ki, *p_wi, *p_top, *p_attn;
    cudaGetSymbolAddress(&p_qkv,  g_qkv);
    cudaGetSymbolAddress(&p_qi,   g_qi);
    cudaGetSymbolAddress(&p_ki,   g_ki);
    cudaGetSymbolAddress(&p_wi,   g_wi);
    cudaGetSymbolAddress(&p_top,  g_topidx);
    cudaGetSymbolAddress(&p_attn, g_attn);

    // 1) qkv projection — tensor cores (bf16 3-term split, full K)
    wmma_gemm<<<dim3(3 * DD / 128, ROWS / 128), 256>>>(x, w_qkv, (float*)p_qkv, 3 * DD);
    // indexer projections — exact fp32 (top-k determinism)
    gemm_small_fused<<<dim3(4, ROWS / 64, 3), 256>>>(x, w_qi, w_ki, w_wi,
                                                     (float*)p_qi, (float*)p_ki, (float*)p_wi,
                                                     ROWS, DD);

    // 2) RoPE
    int rope_total = ROWS * HD * 32;
    rope_kernel<<<(rope_total + 255) / 256, 256>>>((float*)p_qkv);

    // 3) indexer + top-k
    indexer_topk<<<ROWS, 256>>>((const float*)p_qi, (const float*)p_ki,
                                (const float*)p_wi, (unsigned short*)p_top);

    // 4) sparse attention
    attn_kernel<<<dim3(HD, ROWS), 128>>>((const float*)p_qkv,
                                         (const unsigned short*)p_top, (float*)p_attn);

    // 5) output projection — tensor cores
    wmma_gemm<<<dim3(DD / 128, ROWS / 128), 256>>>((const float*)p_attn, w_o, out, DD);
}

// round 15
// speedup vs baseline: 1.0632x; 1.0632x over previous
#include <cuda_runtime.h>
#include <cuda_bf16.h>
#include <mma.h>
#include <math.h>
#include <math_constants.h>
#include <stdint.h>

using namespace nvcuda;

#define BD   2
#define SD   2048
#define DD   1024
#define HD   16
#define DKD  64
#define HID  4
#define DID  64
#define KTOP 512
#define ROWS (BD*SD)

// ---------------- scratch ----------------
__device__ float g_qkv[(size_t)ROWS * 3 * DD];
__device__ float g_qi [(size_t)ROWS * HID * DID];
__device__ float g_ki [(size_t)ROWS * DID];
__device__ float g_wi [(size_t)ROWS * HID];
__device__ unsigned short g_topidx[(size_t)ROWS * KTOP];
__device__ float g_attn[(size_t)ROWS * DD];

// ---------------- WMMA bf16 3-term-split GEMM (FULL K) ----------------
__global__ __launch_bounds__(256) void wmma_gemm(
    const float* __restrict__ A, const float* __restrict__ B,
    float* __restrict__ C, int N)
{
    __shared__ __align__(256) __nv_bfloat16 sA1[128 * 40];
    __shared__ __align__(256) __nv_bfloat16 sA2[128 * 40];
    __shared__ __align__(256) __nv_bfloat16 sB1[128 * 40];
    __shared__ __align__(256) __nv_bfloat16 sB2[128 * 40];
    const int LDS_ELE = 40;
    int tid = threadIdx.x, wid = tid >> 5;
    int bm = blockIdx.y * 128, bn = blockIdx.x * 128;
    int wm = (wid & 3) * 32, wn = (wid >> 2) * 64;

    wmma::fragment<wmma::accumulator, 16, 16, 16, float> acc[2][4];
    #pragma unroll
    for (int mt = 0; mt < 2; mt++)
        #pragma unroll
        for (int nt = 0; nt < 4; nt++)
            wmma::fill_fragment(acc[mt][nt], 0.0f);

    for (int c = 0; c < 32; c++) {
        int k0 = c * 32;
        #pragma unroll
        for (int p = 0; p < 4; p++) {
            int idx = tid + p * 256;
            int row = idx >> 3;
            int cg  = idx & 7;
            int so  = row * LDS_ELE + cg * 4;
            float4 av = *(const float4*)(A + (size_t)(bm + row) * 1024 + k0 + cg * 4);
            __nv_bfloat16 hx = __float2bfloat16(av.x), hy = __float2bfloat16(av.y);
            __nv_bfloat16 hz = __float2bfloat16(av.z), hw = __float2bfloat16(av.w);
            sA1[so] = hx; sA1[so + 1] = hy; sA1[so + 2] = hz; sA1[so + 3] = hw;
            sA2[so]     = __float2bfloat16(av.x - __bfloat162float(hx));
            sA2[so + 1] = __float2bfloat16(av.y - __bfloat162float(hy));
            sA2[so + 2] = __float2bfloat16(av.z - __bfloat162float(hz));
            sA2[so + 3] = __float2bfloat16(av.w - __bfloat162float(hw));
            float4 bv = *(const float4*)(B + (size_t)(bn + row) * 1024 + k0 + cg * 4);
            __nv_bfloat16 gx = __float2bfloat16(bv.x), gy = __float2bfloat16(bv.y);
            __nv_bfloat16 gz = __float2bfloat16(bv.z), gw = __float2bfloat16(bv.w);
            sB1[so] = gx; sB1[so + 1] = gy; sB1[so + 2] = gz; sB1[so + 3] = gw;
            sB2[so]     = __float2bfloat16(bv.x - __bfloat162float(gx));
            sB2[so + 1] = __float2bfloat16(bv.y - __bfloat162float(gy));
            sB2[so + 2] = __float2bfloat16(bv.z - __bfloat162float(gz));
            sB2[so + 3] = __float2bfloat16(bv.w - __bfloat162float(gw));
        }
        __syncthreads();
        #pragma unroll
        for (int kk = 0; kk < 32; kk += 16) {
            wmma::fragment<wmma::matrix_a, 16, 16, 16, __nv_bfloat16, wmma::row_major> a1f[2], a2f[2];
            #pragma unroll
            for (int mt = 0; mt < 2; mt++) {
                int off = (wm + mt * 16) * LDS_ELE + kk;
                wmma::load_matrix_sync(a1f[mt], sA1 + off, LDS_ELE);
                wmma::load_matrix_sync(a2f[mt], sA2 + off, LDS_ELE);
            }
            #pragma unroll
            for (int nt = 0; nt < 4; nt++) {
                int off = (wn + nt * 16) * LDS_ELE + kk;
                wmma::fragment<wmma::matrix_b, 16, 16, 16, __nv_bfloat16, wmma::col_major> b1f, b2f;
                wmma::load_matrix_sync(b1f, sB1 + off, LDS_ELE);
                wmma::load_matrix_sync(b2f, sB2 + off, LDS_ELE);
                #pragma unroll
                for (int mt = 0; mt < 2; mt++) {
                    wmma::mma_sync(acc[mt][nt], a1f[mt], b1f, acc[mt][nt]);
                    wmma::mma_sync(acc[mt][nt], a1f[mt], b2f, acc[mt][nt]);
                    wmma::mma_sync(acc[mt][nt], a2f[mt], b1f, acc[mt][nt]);
                }
            }
        }
        __syncthreads();
    }

    #pragma unroll
    for (int mt = 0; mt < 2; mt++)
        #pragma unroll
        for (int nt = 0; nt < 4; nt++) {
            float* cp = C + (size_t)(bm + wm + mt * 16) * N + bn + wn + nt * 16;
            wmma::store_matrix_sync(cp, acc[mt][nt], N, wmma::mem_row_major);
        }
}

// ---------------- small fused SGEMM (qi, ki, wi) — exact fp32 ----------------
__global__ void gemm_small_fused(const float* __restrict__ A,
                                 const float* __restrict__ B0, const float* __restrict__ B1,
                                 const float* __restrict__ B2,
                                 float* __restrict__ C0, float* __restrict__ C1,
                                 float* __restrict__ C2, int M, int Kd)
{
    const float* B; float* C; int N;
    if (blockIdx.z == 0)      { B = B0; C = C0; N = 256; }
    else if (blockIdx.z == 1) { B = B1; C = C1; N = 64;  }
    else                      { B = B2; C = C2; N = 4;   }
    int bn = blockIdx.x * 64;
    if (bn >= N) return;

    __shared__ float As[16][65];
    __shared__ float Bs[16][65];
    int tid = threadIdx.x;
    int tx = tid & 15, ty = tid >> 4;
    int bm = blockIdx.y * 64;
    float acc[4][4] = {};
    for (int k0 = 0; k0 < Kd; k0 += 16) {
        #pragma unroll
        for (int i = 0; i < 4; i++) {
            int idx = tid + i * 256;
            int m = idx >> 4, k = idx & 15;
            As[k][m] = A[(size_t)(bm + m) * Kd + k0 + k];
            int gn = bn + m;
            Bs[k][m] = (gn < N) ? B[(size_t)gn * Kd + k0 + k] : 0.0f;
        }
        __syncthreads();
        #pragma unroll
        for (int k = 0; k < 16; k++) {
            float a[4], b[4];
            #pragma unroll
            for (int i = 0; i < 4; i++) a[i] = As[k][ty * 4 + i];
            #pragma unroll
            for (int j = 0; j < 4; j++) b[j] = Bs[k][tx * 4 + j];
            #pragma unroll
            for (int i = 0; i < 4; i++)
                #pragma unroll
                for (int j = 0; j < 4; j++)
                    acc[i][j] = fmaf(a[i], b[j], acc[i][j]);
        }
        __syncthreads();
    }
    #pragma unroll
    for (int i = 0; i < 4; i++) {
        int gm = bm + ty * 4 + i;
        #pragma unroll
        for (int j = 0; j < 4; j++) {
            int gn = bn + tx * 4 + j;
            if (gn < N) C[(size_t)gm * N + gn] = acc[i][j];
        }
    }
}

// ---------------- RoPE ----------------
__global__ void rope_kernel(float* __restrict__ qkv) {
    int idx = blockIdx.x * blockDim.x + threadIdx.x;
    if (idx >= ROWS * HD * 32) return;
    int i  = idx & 31;
    int h  = (idx >> 5) & 15;
    int ts = idx >> 9;
    int t  = ts & (SD - 1);
    float inv = (float)(1.0 / pow(10000.0, (double)(2 * i) / 64.0));
    float ang = (float)t * inv;
    float c = cosf(ang), s = sinf(ang);
    size_t base = (size_t)ts * 3072 + h * 64 + 2 * i;
    float x1 = qkv[base], x2 = qkv[base + 1];
    qkv[base]     = x1 * c - x2 * s;
    qkv[base + 1] = x1 * s + x2 * c;
    x1 = qkv[base + 1024]; x2 = qkv[base + 1025];
    qkv[base + 1024] = x1 * c - x2 * s;
    qkv[base + 1025] = x1 * s + x2 * c;
}

__device__ __forceinline__ unsigned int fkey(float f) {
    unsigned int u = __float_as_uint(f);
    return (u & 0x80000000u) ? ~u : (u | 0x80000000u);
}

// ---------------- indexer + exact top-k (R13 verbatim — 40 regs, occ 70%) ----------------
__global__ void indexer_topk(const float* __restrict__ qi, const float* __restrict__ ki,
                             const float* __restrict__ wi, unsigned short* __restrict__ topidx) {
    int r = blockIdx.x;
    int b = r >> 11;
    int t = r & (SD - 1);
    int tid = threadIdx.x;
    __shared__ float sc[SD];
    __shared__ __align__(16) float qis[HID * DID];
    __shared__ float wis[HID];
    __shared__ unsigned int hist[256];
    __shared__ unsigned int scanbuf[256];
    __shared__ unsigned int sh_prefix, sh_kneed, sh_outcnt;

    qis[tid] = qi[(size_t)r * 256 + tid];
    if (tid < 4) wis[tid] = wi[r * 4 + tid];
    if (tid == 0) { sh_prefix = 0u; sh_kneed = KTOP; sh_outcnt = 0u; }
    __syncthreads();

    const float* kbase = ki + (size_t)b * SD * DID;
    const float4* q4 = (const float4*)qis;
    for (int rr = 0; rr < 8; rr++) {
        int s = tid + rr * 256;
        float val;
        if (s > t) {
            val = -CUDART_INF_F;
        } else {
            const float4* kp4 = (const float4*)(kbase + (size_t)s * DID);
            float d0 = 0, d1 = 0, d2 = 0, d3 = 0;
            #pragma unroll
            for (int d4 = 0; d4 < 16; d4++) {
                float4 kv = kp4[d4];
                float4 a0 = q4[d4], a1 = q4[16 + d4], a2 = q4[32 + d4], a3 = q4[48 + d4];
                d0 = fmaf(a0.x, kv.x, d0); d0 = fmaf(a0.y, kv.y, d0);
                d0 = fmaf(a0.z, kv.z, d0); d0 = fmaf(a0.w, kv.w, d0);
                d1 = fmaf(a1.x, kv.x, d1); d1 = fmaf(a1.y, kv.y, d1);
                d1 = fmaf(a1.z, kv.z, d1); d1 = fmaf(a1.w, kv.w, d1);
                d2 = fmaf(a2.x, kv.x, d2); d2 = fmaf(a2.y, kv.y, d2);
                d2 = fmaf(a2.z, kv.z, d2); d2 = fmaf(a2.w, kv.w, d2);
                d3 = fmaf(a3.x, kv.x, d3); d3 = fmaf(a3.y, kv.y, d3);
                d3 = fmaf(a3.z, kv.z, d3); d3 = fmaf(a3.w, kv.w, d3);
            }
            val = fmaxf(d0, 0.f) * wis[0] + fmaxf(d1, 0.f) * wis[1]
                + fmaxf(d2, 0.f) * wis[2] + fmaxf(d3, 0.f) * wis[3];
            val += 0.0f;
        }
        sc[s] = val;
    }
    __syncthreads();

    unsigned int prefix = 0, maskdone = 0;
    for (int shift = 24; shift >= 0; shift -= 8) {
        hist[tid] = 0;
        __syncthreads();
        for (int rr = 0; rr < 8; rr++) {
            int s = tid * 8 + rr;
            unsigned int key = fkey(sc[s]);
            if ((key & maskdone) == prefix) atomicAdd(&hist[(key >> shift) & 255], 1u);
        }
        __syncthreads();
        if (tid == 0) {
            unsigned int kneed = sh_kneed, c = 0;
            int bsel = 0;
            for (int bb = 255; bb >= 0; bb--) {
                unsigned int c2 = c + hist[bb];
                if (c2 >= kneed) { bsel = bb; break; }
                c = c2;
            }
            sh_kneed  = kneed - c;
            sh_prefix = sh_prefix | ((unsigned int)bsel << shift);
        }
        __syncthreads();
        prefix = sh_prefix;
        maskdone |= (255u << shift);
    }
    unsigned int T    = prefix;
    unsigned int n_eq = sh_kneed;

    unsigned int eqc = 0;
    for (int rr = 0; rr < 8; rr++) {
        int s = tid * 8 + rr;
        if (fkey(sc[s]) == T) eqc++;
    }
    scanbuf[tid] = eqc;
    __syncthreads();
    for (int off = 1; off < 256; off <<= 1) {
        unsigned int v = scanbuf[tid];
        unsigned int add = (tid >= off) ? scanbuf[tid - off] : 0u;
        __syncthreads();
        scanbuf[tid] = v + add;
        __syncthreads();
    }
    unsigned int rank = scanbuf[tid] - eqc;

    unsigned short* outp = topidx + (size_t)r * KTOP;
    for (int rr = 0; rr < 8; rr++) {
        int s = tid * 8 + rr;
        unsigned int key = fkey(sc[s]);
        if (key > T) {
            unsigned int p = atomicAdd(&sh_outcnt, 1u);
            outp[p] = (unsigned short)s;
        } else if (key == T) {
            if (rank < n_eq) {
                unsigned int p = atomicAdd(&sh_outcnt, 1u);
                outp[p] = (unsigned short)s;
            }
            rank++;
        }
    }
}

// ---------------- gathered sparse attention (R14 8-deep MLP — kept) ----------------
__global__ void attn_kernel(const float* __restrict__ qkv,
                            const unsigned short* __restrict__ topidx,
                            float* __restrict__ attn_out) {
    int h   = blockIdx.x;
    int row = blockIdx.y;
    int b   = row >> 11;
    int tid  = threadIdx.x;
    int lane = tid & 31, w = tid >> 5;

    __shared__ float q[64];
    __shared__ float sc[KTOP];
    __shared__ int   sidx[KTOP];
    __shared__ float redm[4], redsum[4];
    __shared__ float part[128];

    const unsigned short* ip = topidx + (size_t)row * KTOP;
    #pragma unroll
    for (int r = 0; r < 4; r++) sidx[tid + 128 * r] = (int)ip[tid + 128 * r];
    if (tid < 64) q[tid] = qkv[(size_t)row * 3072 + h * 64 + tid];
    __syncthreads();

    float qx = q[2 * lane], qy = q[2 * lane + 1];
    const float* kb = qkv + (size_t)b * SD * 3072 + 1024 + h * 64 + 2 * lane;
    float mloc = -CUDART_INF_F;
    int j0 = w * 128;
    for (int jj = 0; jj < 128; jj += 8) {
        int j = j0 + jj;
        float d[8];
        #pragma unroll
        for (int u = 0; u < 8; u++) {
            float2 kv = *(const float2*)(kb + (size_t)sidx[j + u] * 3072);
            d[u] = fmaf(qx, kv.x, qy * kv.y);
        }
        #pragma unroll
        for (int u = 0; u < 8; u++) {
            #pragma unroll
            for (int o = 16; o; o >>= 1) d[u] += __shfl_xor_sync(0xffffffffu, d[u], o);
            d[u] *= 0.125f;
            mloc = fmaxf(mloc, d[u]);
        }
        if (lane < 8) sc[j + lane] = d[lane];
    }
    if (lane == 0) redm[w] = mloc;
    __syncthreads();
    float m = fmaxf(fmaxf(redm[0], redm[1]), fmaxf(redm[2], redm[3]));

    float sloc = 0.f;
    #pragma unroll
    for (int r = 0; r < 4; r++) {
        int j = tid + 128 * r;
        float e = expf(sc[j] - m);
        sc[j] = e;
        sloc += e;
    }
    #pragma unroll
    for (int o = 16; o; o >>= 1) sloc += __shfl_xor_sync(0xffffffffu, sloc, o);
    if (lane == 0) redsum[w] = sloc;
    __syncthreads();
    float inv = 1.0f / (redsum[0] + redsum[1] + redsum[2] + redsum[3]);

    int d    = tid & 63;
    int half = tid >> 6;
    const float* vb = qkv + (size_t)b * SD * 3072 + 2048 + h * 64 + d;
    float a[8];
    #pragma unroll
    for (int u = 0; u < 8; u++) a[u] = 0.f;
    int jb = half * 256;
    for (int j = jb; j < jb + 256; j += 8) {
        #pragma unroll
        for (int u = 0; u < 8; u++)
            a[u] = fmaf(sc[j + u], vb[(size_t)sidx[j + u] * 3072], a[u]);
    }
    part[tid] = ((a[0] + a[1]) + (a[2] + a[3])) + ((a[4] + a[5]) + (a[6] + a[7]));
    __syncthreads();
    if (tid < 64)
        attn_out[(size_t)row * DD + h * 64 + tid] = (part[tid] + part[tid + 64]) * inv;
}

// ---------------- launch ----------------
extern "C" void kernel_launch(void* const* d_in, const int* in_sizes, int n_in,
                              void* d_out, int out_size) {
    const float* x     = (const float*)d_in[0];
    const float* w_qkv = (const float*)d_in[1];
    const float* w_o   = (const float*)d_in[2];
    const float* w_qi  = (const float*)d_in[3];
    const float* w_ki  = (const float*)d_in[4];
    const float* w_wi  = (const float*)d_in[5];
    float* out = (float*)d_out;

    void *p_qkv, *p_qi, *p_ki, *p_wi, *p_top, *p_attn;
    cudaGetSymbolAddress(&p_qkv,  g_qkv);
    cudaGetSymbolAddress(&p_qi,   g_qi);
    cudaGetSymbolAddress(&p_ki,   g_ki);
    cudaGetSymbolAddress(&p_wi,   g_wi);
    cudaGetSymbolAddress(&p_top,  g_topidx);
    cudaGetSymbolAddress(&p_attn, g_attn);

    // 1) qkv projection — tensor cores (bf16 3-term split, full K)
    wmma_gemm<<<dim3(3 * DD / 128, ROWS / 128), 256>>>(x, w_qkv, (float*)p_qkv, 3 * DD);
    // indexer projections — exact fp32 (top-k determinism)
    gemm_small_fused<<<dim3(4, ROWS / 64, 3), 256>>>(x, w_qi, w_ki, w_wi,
                                                     (float*)p_qi, (float*)p_ki, (float*)p_wi,
                                                     ROWS, DD);

    // 2) RoPE
    int rope_total = ROWS * HD * 32;
    rope_kernel<<<(rope_total + 255) / 256, 256>>>((float*)p_qkv);

    // 3) indexer + top-k
    indexer_topk<<<ROWS, 256>>>((const float*)p_qi, (const float*)p_ki,
                                (const float*)p_wi, (unsigned short*)p_top);

    // 4) sparse attention
    attn_kernel<<<dim3(HD, ROWS), 128>>>((const float*)p_qkv,
                                         (const unsigned short*)p_top, (float*)p_attn);

    // 5) output projection — tensor cores
    wmma_gemm<<<dim3(DD / 128, ROWS / 128), 256>>>((const float*)p_attn, w_o, out, DD);
}

// round 17
// speedup vs baseline: 1.0974x; 1.0322x over previous
#include <cuda_runtime.h>
#include <cuda_bf16.h>
#include <cuda_fp16.h>
#include <mma.h>
#include <math.h>
#include <math_constants.h>
#include <stdint.h>

using namespace nvcuda;

#define BD   2
#define SD   2048
#define DD   1024
#define HD   16
#define DKD  64
#define HID  4
#define DID  64
#define KTOP 512
#define ROWS (BD*SD)

// ---------------- scratch ----------------
__device__ float g_qkv[(size_t)ROWS * 3 * DD];
__device__ float g_qi [(size_t)ROWS * HID * DID];
__device__ float g_ki [(size_t)ROWS * DID];
__device__ float g_wi [(size_t)ROWS * HID];
__device__ unsigned short g_topidx[(size_t)ROWS * KTOP];
__device__ float g_attn[(size_t)ROWS * DD];
// post-RoPE fp16 shadow of K|V: per row 2048 halfs = [k(1024) | v(1024)], head-major
__device__ __half g_kv16[(size_t)ROWS * 2 * DD];

// ---------------- WMMA bf16 3-term-split GEMM (FULL K) ----------------
__global__ __launch_bounds__(256) void wmma_gemm(
    const float* __restrict__ A, const float* __restrict__ B,
    float* __restrict__ C, int N)
{
    __shared__ __align__(256) __nv_bfloat16 sA1[128 * 40];
    __shared__ __align__(256) __nv_bfloat16 sA2[128 * 40];
    __shared__ __align__(256) __nv_bfloat16 sB1[128 * 40];
    __shared__ __align__(256) __nv_bfloat16 sB2[128 * 40];
    const int LDS_ELE = 40;
    int tid = threadIdx.x, wid = tid >> 5;
    int bm = blockIdx.y * 128, bn = blockIdx.x * 128;
    int wm = (wid & 3) * 32, wn = (wid >> 2) * 64;

    wmma::fragment<wmma::accumulator, 16, 16, 16, float> acc[2][4];
    #pragma unroll
    for (int mt = 0; mt < 2; mt++)
        #pragma unroll
        for (int nt = 0; nt < 4; nt++)
            wmma::fill_fragment(acc[mt][nt], 0.0f);

    for (int c = 0; c < 32; c++) {
        int k0 = c * 32;
        #pragma unroll
        for (int p = 0; p < 4; p++) {
            int idx = tid + p * 256;
            int row = idx >> 3;
            int cg  = idx & 7;
            int so  = row * LDS_ELE + cg * 4;
            float4 av = *(const float4*)(A + (size_t)(bm + row) * 1024 + k0 + cg * 4);
            __nv_bfloat16 hx = __float2bfloat16(av.x), hy = __float2bfloat16(av.y);
            __nv_bfloat16 hz = __float2bfloat16(av.z), hw = __float2bfloat16(av.w);
            sA1[so] = hx; sA1[so + 1] = hy; sA1[so + 2] = hz; sA1[so + 3] = hw;
            sA2[so]     = __float2bfloat16(av.x - __bfloat162float(hx));
            sA2[so + 1] = __float2bfloat16(av.y - __bfloat162float(hy));
            sA2[so + 2] = __float2bfloat16(av.z - __bfloat162float(hz));
            sA2[so + 3] = __float2bfloat16(av.w - __bfloat162float(hw));
            float4 bv = *(const float4*)(B + (size_t)(bn + row) * 1024 + k0 + cg * 4);
            __nv_bfloat16 gx = __float2bfloat16(bv.x), gy = __float2bfloat16(bv.y);
            __nv_bfloat16 gz = __float2bfloat16(bv.z), gw = __float2bfloat16(bv.w);
            sB1[so] = gx; sB1[so + 1] = gy; sB1[so + 2] = gz; sB1[so + 3] = gw;
            sB2[so]     = __float2bfloat16(bv.x - __bfloat162float(gx));
            sB2[so + 1] = __float2bfloat16(bv.y - __bfloat162float(gy));
            sB2[so + 2] = __float2bfloat16(bv.z - __bfloat162float(gz));
            sB2[so + 3] = __float2bfloat16(bv.w - __bfloat162float(gw));
        }
        __syncthreads();
        #pragma unroll
        for (int kk = 0; kk < 32; kk += 16) {
            wmma::fragment<wmma::matrix_a, 16, 16, 16, __nv_bfloat16, wmma::row_major> a1f[2], a2f[2];
            #pragma unroll
            for (int mt = 0; mt < 2; mt++) {
                int off = (wm + mt * 16) * LDS_ELE + kk;
                wmma::load_matrix_sync(a1f[mt], sA1 + off, LDS_ELE);
                wmma::load_matrix_sync(a2f[mt], sA2 + off, LDS_ELE);
            }
            #pragma unroll
            for (int nt = 0; nt < 4; nt++) {
                int off = (wn + nt * 16) * LDS_ELE + kk;
                wmma::fragment<wmma::matrix_b, 16, 16, 16, __nv_bfloat16, wmma::col_major> b1f, b2f;
                wmma::load_matrix_sync(b1f, sB1 + off, LDS_ELE);
                wmma::load_matrix_sync(b2f, sB2 + off, LDS_ELE);
                #pragma unroll
                for (int mt = 0; mt < 2; mt++) {
                    wmma::mma_sync(acc[mt][nt], a1f[mt], b1f, acc[mt][nt]);
                    wmma::mma_sync(acc[mt][nt], a1f[mt], b2f, acc[mt][nt]);
                    wmma::mma_sync(acc[mt][nt], a2f[mt], b1f, acc[mt][nt]);
                }
            }
        }
        __syncthreads();
    }

    #pragma unroll
    for (int mt = 0; mt < 2; mt++)
        #pragma unroll
        for (int nt = 0; nt < 4; nt++) {
            float* cp = C + (size_t)(bm + wm + mt * 16) * N + bn + wn + nt * 16;
            wmma::store_matrix_sync(cp, acc[mt][nt], N, wmma::mem_row_major);
        }
}

// ---------------- small fused SGEMM (qi, ki, wi) — exact fp32 ----------------
__global__ void gemm_small_fused(const float* __restrict__ A,
                                 const float* __restrict__ B0, const float* __restrict__ B1,
                                 const float* __restrict__ B2,
                                 float* __restrict__ C0, float* __restrict__ C1,
                                 float* __restrict__ C2, int M, int Kd)
{
    const float* B; float* C; int N;
    if (blockIdx.z == 0)      { B = B0; C = C0; N = 256; }
    else if (blockIdx.z == 1) { B = B1; C = C1; N = 64;  }
    else                      { B = B2; C = C2; N = 4;   }
    int bn = blockIdx.x * 64;
    if (bn >= N) return;

    __shared__ float As[16][65];
    __shared__ float Bs[16][65];
    int tid = threadIdx.x;
    int tx = tid & 15, ty = tid >> 4;
    int bm = blockIdx.y * 64;
    float acc[4][4] = {};
    for (int k0 = 0; k0 < Kd; k0 += 16) {
        #pragma unroll
        for (int i = 0; i < 4; i++) {
            int idx = tid + i * 256;
            int m = idx >> 4, k = idx & 15;
            As[k][m] = A[(size_t)(bm + m) * Kd + k0 + k];
            int gn = bn + m;
            Bs[k][m] = (gn < N) ? B[(size_t)gn * Kd + k0 + k] : 0.0f;
        }
        __syncthreads();
        #pragma unroll
        for (int k = 0; k < 16; k++) {
            float a[4], b[4];
            #pragma unroll
            for (int i = 0; i < 4; i++) a[i] = As[k][ty * 4 + i];
            #pragma unroll
            for (int j = 0; j < 4; j++) b[j] = Bs[k][tx * 4 + j];
            #pragma unroll
            for (int i = 0; i < 4; i++)
                #pragma unroll
                for (int j = 0; j < 4; j++)
                    acc[i][j] = fmaf(a[i], b[j], acc[i][j]);
        }
        __syncthreads();
    }
    #pragma unroll
    for (int i = 0; i < 4; i++) {
        int gm = bm + ty * 4 + i;
        #pragma unroll
        for (int j = 0; j < 4; j++) {
            int gn = bn + tx * 4 + j;
            if (gn < N) C[(size_t)gm * N + gn] = acc[i][j];
        }
    }
}

// ---------------- RoPE ----------------
__global__ void rope_kernel(float* __restrict__ qkv) {
    int idx = blockIdx.x * blockDim.x + threadIdx.x;
    if (idx >= ROWS * HD * 32) return;
    int i  = idx & 31;
    int h  = (idx >> 5) & 15;
    int ts = idx >> 9;
    int t  = ts & (SD - 1);
    float inv = (float)(1.0 / pow(10000.0, (double)(2 * i) / 64.0));
    float ang = (float)t * inv;
    float c = cosf(ang), s = sinf(ang);
    size_t base = (size_t)ts * 3072 + h * 64 + 2 * i;
    float x1 = qkv[base], x2 = qkv[base + 1];
    qkv[base]     = x1 * c - x2 * s;
    qkv[base + 1] = x1 * s + x2 * c;
    x1 = qkv[base + 1024]; x2 = qkv[base + 1025];
    qkv[base + 1024] = x1 * c - x2 * s;
    qkv[base + 1025] = x1 * s + x2 * c;
}

// ---------------- K|V fp32 -> fp16 shadow (post-RoPE) ----------------
__global__ void kv_to_fp16(const float* __restrict__ qkv, __half* __restrict__ kv16) {
    int i4 = blockIdx.x * blockDim.x + threadIdx.x;     // over ROWS*2048/4
    if (i4 >= ROWS * 512) return;
    int row = i4 >> 9;
    int c4  = (i4 & 511) * 4;
    float4 v = *(const float4*)(qkv + (size_t)row * 3072 + 1024 + c4);
    __half2 lo = __floats2half2_rn(v.x, v.y);
    __half2 hi = __floats2half2_rn(v.z, v.w);
    *(__half2*)(kv16 + (size_t)row * 2048 + c4)     = lo;
    *(__half2*)(kv16 + (size_t)row * 2048 + c4 + 2) = hi;
}

__device__ __forceinline__ unsigned int fkey(float f) {
    unsigned int u = __float_as_uint(f);
    return (u & 0x80000000u) ? ~u : (u | 0x80000000u);
}

// ---------------- indexer + exact top-k (R15 verbatim) ----------------
__global__ void indexer_topk(const float* __restrict__ qi, const float* __restrict__ ki,
                             const float* __restrict__ wi, unsigned short* __restrict__ topidx) {
    int r = blockIdx.x;
    int b = r >> 11;
    int t = r & (SD - 1);
    int tid = threadIdx.x;
    __shared__ float sc[SD];
    __shared__ __align__(16) float qis[HID * DID];
    __shared__ float wis[HID];
    __shared__ unsigned int hist[256];
    __shared__ unsigned int scanbuf[256];
    __shared__ unsigned int sh_prefix, sh_kneed, sh_outcnt;

    qis[tid] = qi[(size_t)r * 256 + tid];
    if (tid < 4) wis[tid] = wi[r * 4 + tid];
    if (tid == 0) { sh_prefix = 0u; sh_kneed = KTOP; sh_outcnt = 0u; }
    __syncthreads();

    const float* kbase = ki + (size_t)b * SD * DID;
    const float4* q4 = (const float4*)qis;
    for (int rr = 0; rr < 8; rr++) {
        int s = tid + rr * 256;
        float val;
        if (s > t) {
            val = -CUDART_INF_F;
        } else {
            const float4* kp4 = (const float4*)(kbase + (size_t)s * DID);
            float d0 = 0, d1 = 0, d2 = 0, d3 = 0;
            #pragma unroll
            for (int d4 = 0; d4 < 16; d4++) {
                float4 kv = kp4[d4];
                float4 a0 = q4[d4], a1 = q4[16 + d4], a2 = q4[32 + d4], a3 = q4[48 + d4];
                d0 = fmaf(a0.x, kv.x, d0); d0 = fmaf(a0.y, kv.y, d0);
                d0 = fmaf(a0.z, kv.z, d0); d0 = fmaf(a0.w, kv.w, d0);
                d1 = fmaf(a1.x, kv.x, d1); d1 = fmaf(a1.y, kv.y, d1);
                d1 = fmaf(a1.z, kv.z, d1); d1 = fmaf(a1.w, kv.w, d1);
                d2 = fmaf(a2.x, kv.x, d2); d2 = fmaf(a2.y, kv.y, d2);
                d2 = fmaf(a2.z, kv.z, d2); d2 = fmaf(a2.w, kv.w, d2);
                d3 = fmaf(a3.x, kv.x, d3); d3 = fmaf(a3.y, kv.y, d3);
                d3 = fmaf(a3.z, kv.z, d3); d3 = fmaf(a3.w, kv.w, d3);
            }
            val = fmaxf(d0, 0.f) * wis[0] + fmaxf(d1, 0.f) * wis[1]
                + fmaxf(d2, 0.f) * wis[2] + fmaxf(d3, 0.f) * wis[3];
            val += 0.0f;
        }
        sc[s] = val;
    }
    __syncthreads();

    unsigned int prefix = 0, maskdone = 0;
    for (int shift = 24; shift >= 0; shift -= 8) {
        hist[tid] = 0;
        __syncthreads();
        for (int rr = 0; rr < 8; rr++) {
            int s = tid * 8 + rr;
            unsigned int key = fkey(sc[s]);
            if ((key & maskdone) == prefix) atomicAdd(&hist[(key >> shift) & 255], 1u);
        }
        __syncthreads();
        if (tid == 0) {
            unsigned int kneed = sh_kneed, c = 0;
            int bsel = 0;
            for (int bb = 255; bb >= 0; bb--) {
                unsigned int c2 = c + hist[bb];
                if (c2 >= kneed) { bsel = bb; break; }
                c = c2;
            }
            sh_kneed  = kneed - c;
            sh_prefix = sh_prefix | ((unsigned int)bsel << shift);
        }
        __syncthreads();
        prefix = sh_prefix;
        maskdone |= (255u << shift);
    }
    unsigned int T    = prefix;
    unsigned int n_eq = sh_kneed;

    unsigned int eqc = 0;
    for (int rr = 0; rr < 8; rr++) {
        int s = tid * 8 + rr;
        if (fkey(sc[s]) == T) eqc++;
    }
    scanbuf[tid] = eqc;
    __syncthreads();
    for (int off = 1; off < 256; off <<= 1) {
        unsigned int v = scanbuf[tid];
        unsigned int add = (tid >= off) ? scanbuf[tid - off] : 0u;
        __syncthreads();
        scanbuf[tid] = v + add;
        __syncthreads();
    }
    unsigned int rank = scanbuf[tid] - eqc;

    unsigned short* outp = topidx + (size_t)r * KTOP;
    for (int rr = 0; rr < 8; rr++) {
        int s = tid * 8 + rr;
        unsigned int key = fkey(sc[s]);
        if (key > T) {
            unsigned int p = atomicAdd(&sh_outcnt, 1u);
            outp[p] = (unsigned short)s;
        } else if (key == T) {
            if (rank < n_eq) {
                unsigned int p = atomicAdd(&sh_outcnt, 1u);
                outp[p] = (unsigned short)s;
            }
            rank++;
        }
    }
}

// ---------------- gathered sparse attention (fp16 K/V gather, fp32 accum) ----------------
__global__ void attn_kernel(const float* __restrict__ qkv,
                            const __half* __restrict__ kv16,
                            const unsigned short* __restrict__ topidx,
                            float* __restrict__ attn_out) {
    int h   = blockIdx.x;
    int row = blockIdx.y;
    int b   = row >> 11;
    int tid  = threadIdx.x;
    int lane = tid & 31, w = tid >> 5;

    __shared__ float q[64];
    __shared__ float sc[KTOP];
    __shared__ int   sidx[KTOP];
    __shared__ float redm[4], redsum[4];
    __shared__ float part[128];

    const unsigned short* ip = topidx + (size_t)row * KTOP;
    #pragma unroll
    for (int r = 0; r < 4; r++) sidx[tid + 128 * r] = (int)ip[tid + 128 * r];
    if (tid < 64) q[tid] = qkv[(size_t)row * 3072 + h * 64 + tid];
    __syncthreads();

    // score phase: warp w -> keys [w*128, w*128+128); 8 keys in flight; fp16 K
    float qx = q[2 * lane], qy = q[2 * lane + 1];
    const __half* kb = kv16 + (size_t)b * SD * 2048 + h * 64 + 2 * lane;
    float mloc = -CUDART_INF_F;
    int j0 = w * 128;
    for (int jj = 0; jj < 128; jj += 8) {
        int j = j0 + jj;
        float d[8];
        #pragma unroll
        for (int u = 0; u < 8; u++) {
            __half2 kv = *(const __half2*)(kb + (size_t)sidx[j + u] * 2048);
            float2 kf = __half22float2(kv);
            d[u] = fmaf(qx, kf.x, qy * kf.y);
        }
        #pragma unroll
        for (int u = 0; u < 8; u++) {
            #pragma unroll
            for (int o = 16; o; o >>= 1) d[u] += __shfl_xor_sync(0xffffffffu, d[u], o);
            d[u] *= 0.125f;
            mloc = fmaxf(mloc, d[u]);
        }
        if (lane < 8) sc[j + lane] = d[lane];
    }
    if (lane == 0) redm[w] = mloc;
    __syncthreads();
    float m = fmaxf(fmaxf(redm[0], redm[1]), fmaxf(redm[2], redm[3]));

    float sloc = 0.f;
    #pragma unroll
    for (int r = 0; r < 4; r++) {
        int j = tid + 128 * r;
        float e = expf(sc[j] - m);
        sc[j] = e;
        sloc += e;
    }
    #pragma unroll
    for (int o = 16; o; o >>= 1) sloc += __shfl_xor_sync(0xffffffffu, sloc, o);
    if (lane == 0) redsum[w] = sloc;
    __syncthreads();
    float inv = 1.0f / (redsum[0] + redsum[1] + redsum[2] + redsum[3]);

    // V phase: 8 independent accumulators; fp16 V
    int d    = tid & 63;
    int half = tid >> 6;
    const __half* vb = kv16 + (size_t)b * SD * 2048 + 1024 + h * 64 + d;
    float a[8];
    #pragma unroll
    for (int u = 0; u < 8; u++) a[u] = 0.f;
    int jb = half * 256;
    for (int j = jb; j < jb + 256; j += 8) {
        #pragma unroll
        for (int u = 0; u < 8; u++)
            a[u] = fmaf(sc[j + u], __half2float(vb[(size_t)sidx[j + u] * 2048]), a[u]);
    }
    part[tid] = ((a[0] + a[1]) + (a[2] + a[3])) + ((a[4] + a[5]) + (a[6] + a[7]));
    __syncthreads();
    if (tid < 64)
        attn_out[(size_t)row * DD + h * 64 + tid] = (part[tid] + part[tid + 64]) * inv;
}

// ---------------- launch ----------------
extern "C" void kernel_launch(void* const* d_in, const int* in_sizes, int n_in,
                              void* d_out, int out_size) {
    const float* x     = (const float*)d_in[0];
    const float* w_qkv = (const float*)d_in[1];
    const float* w_o   = (const float*)d_in[2];
    const float* w_qi  = (const float*)d_in[3];
    const float* w_ki  = (const float*)d_in[4];
    const float* w_wi  = (const float*)d_in[5];
    float* out = (float*)d_out;

    void *p_qkv, *p_qi, *p_ki, *p_wi, *p_top, *p_attn, *p_kv16;
    cudaGetSymbolAddress(&p_qkv,  g_qkv);
    cudaGetSymbolAddress(&p_qi,   g_qi);
    cudaGetSymbolAddress(&p_ki,   g_ki);
    cudaGetSymbolAddress(&p_wi,   g_wi);
    cudaGetSymbolAddress(&p_top,  g_topidx);
    cudaGetSymbolAddress(&p_attn, g_attn);
    cudaGetSymbolAddress(&p_kv16, g_kv16);

    // 1) qkv projection — tensor cores (bf16 3-term split, full K)
    wmma_gemm<<<dim3(3 * DD / 128, ROWS / 128), 256>>>(x, w_qkv, (float*)p_qkv, 3 * DD);
    // indexer projections — exact fp32 (top-k determinism)
    gemm_small_fused<<<dim3(4, ROWS / 64, 3), 256>>>(x, w_qi, w_ki, w_wi,
                                                     (float*)p_qi, (float*)p_ki, (float*)p_wi,
                                                     ROWS, DD);

    // 2) RoPE, then fp16 K|V shadow
    int rope_total = ROWS * HD * 32;
    rope_kernel<<<(rope_total + 255) / 256, 256>>>((float*)p_qkv);
    kv_to_fp16<<<(ROWS * 512 + 255) / 256, 256>>>((const float*)p_qkv, (__half*)p_kv16);

    // 3) indexer + top-k
    indexer_topk<<<ROWS, 256>>>((const float*)p_qi, (const float*)p_ki,
                                (const float*)p_wi, (unsigned short*)p_top);

    // 4) sparse attention (fp16 gather)
    attn_kernel<<<dim3(HD, ROWS), 128>>>((const float*)p_qkv, (const __half*)p_kv16,
                                         (const unsigned short*)p_top, (float*)p_attn);

    // 5) output projection — tensor cores
    wmma_gemm<<<dim3(DD / 128, ROWS / 128), 256>>>((const float*)p_attn, w_o, out, DD);
}